// round 4
// baseline (speedup 1.0000x reference)
#include <cuda_runtime.h>
#include <cuda_bf16.h>
#include <math.h>
#include <stdint.h>

// Problem constants
#define BATCH   2
#define HW      64
#define SEQ     256
#define DMODEL  512
#define HEADS   8
#define DK      64
#define KSIZE   7
#define NEIGH   3

#define MROWS   (BATCH * HW * SEQ)      // 32768
#define QKV_N   (3 * HEADS * DK)        // 1536

// GEMM tiling
#define BM 128
#define BN 128
#define BK 32
#define XS 36                            // smem row stride (floats)
#define GEMM_THREADS 256

// Scratch (allocation-free: __device__ globals)
__device__ float g_xt  [(size_t)MROWS * DMODEL];   //  64 MB (tf32, K-permuted)
__device__ float g_qkv [(size_t)MROWS * QKV_N];    // 201 MB
__device__ float g_att [(size_t)MROWS * DMODEL];   //  67 MB (tf32, K-permuted)
__device__ float g_wqkvT[(size_t)QKV_N * DMODEL];  //   3 MB (Wqkv^T, K-permuted)
__device__ float g_woutT[(size_t)DMODEL * DMODEL]; //   1 MB (Wout^T, K-permuted)

// ---------------------------------------------------------------------------
// Helpers
// ---------------------------------------------------------------------------
__device__ __forceinline__ float to_tf32(float x) {
    float y;
    asm("cvt.rna.tf32.f32 %0, %1;" : "=f"(y) : "f"(x));
    return y;
}

// In-8-chunk K permutation: k -> (k&~7) | ((k&3)<<1) | (k>>2&1).
// Applied to BOTH operands of each GEMM along K, so dot products are invariant.
// Makes mma fragment k-pairs {t, t+4} adjacent in memory -> LDS.64.
__device__ __forceinline__ int permk(int k) {
    return (k & ~7) | ((k & 3) << 1) | ((k >> 2) & 1);
}

__device__ __forceinline__ uint32_t smem_u32(const void* p) {
    uint32_t a;
    asm("{ .reg .u64 t; cvta.to.shared.u64 t, %1; cvt.u32.u64 %0, t; }"
        : "=r"(a) : "l"(p));
    return a;
}

#define CP_ASYNC16(dst, src) \
    asm volatile("cp.async.cg.shared.global [%0], [%1], 16;" \
                 :: "r"(dst), "l"(src) : "memory")
#define CP_COMMIT() asm volatile("cp.async.commit_group;" ::: "memory")
#define CP_WAIT(n)  asm volatile("cp.async.wait_group %0;" :: "n"(n) : "memory")

__device__ __forceinline__ void mma_tf32(float* c, const uint32_t* a,
                                         const uint32_t* b) {
    asm volatile(
        "mma.sync.aligned.m16n8k8.row.col.f32.tf32.tf32.f32 "
        "{%0,%1,%2,%3}, {%4,%5,%6,%7}, {%8,%9}, {%0,%1,%2,%3};"
        : "+f"(c[0]), "+f"(c[1]), "+f"(c[2]), "+f"(c[3])
        : "r"(a[0]), "r"(a[1]), "r"(a[2]), "r"(a[3]),
          "r"(b[0]), "r"(b[1]));
}

// ---------------------------------------------------------------------------
// tf32 warp-MMA GEMM: C[M,N] = A[M,K] @ Bt[N,K]^T  (K-permuted operands)
// CTA 128x128, BK=32, double-buffered cp.async, 8 warps @ 64x32 warp tile.
// __launch_bounds__(256,2): 2 CTAs/SM for latency hiding.
// ---------------------------------------------------------------------------
__global__ __launch_bounds__(GEMM_THREADS, 2) void gemm_mma_tf32(
    const float* __restrict__ A, const float* __restrict__ Bt,
    float* __restrict__ C, int M, int N, int K)
{
    extern __shared__ float sm[];
    float* Asf = sm;                       // [2][BM][XS]
    float* Bsf = sm + 2 * BM * XS;         // [2][BN][XS]
    const uint32_t as_u = smem_u32(Asf);
    const uint32_t bs_u = smem_u32(Bsf);

    const int tid  = threadIdx.x;
    const int wid  = tid >> 5;
    const int lane = tid & 31;
    const int gid  = lane >> 2;    // 0..7
    const int tig  = lane & 3;     // 0..3

    const int wm0 = (wid >> 2) * 64;   // warp m-offset in CTA tile
    const int wn0 = (wid & 3) * 32;    // warp n-offset

    const int mbase = blockIdx.y * BM;
    const int nbase = blockIdx.x * BN;
    const float* Ab = A  + (size_t)mbase * K;
    const float* Bb = Bt + (size_t)nbase * K;

    const int lrow = tid >> 3;          // 0..31
    const int lk4  = (tid & 7) << 2;    // 0,4,...,28

    auto load_stage = [&](int s, int buf) {
        const float* Asrc = Ab + (size_t)s * BK;
        const float* Bsrc = Bb + (size_t)s * BK;
        #pragma unroll
        for (int j = 0; j < 4; j++) {
            int row = lrow + 32 * j;
            uint32_t d = as_u + (((uint32_t)(buf * BM + row) * XS + lk4) << 2);
            CP_ASYNC16(d, Asrc + (size_t)row * K + lk4);
        }
        #pragma unroll
        for (int j = 0; j < 4; j++) {
            int row = lrow + 32 * j;
            uint32_t d = bs_u + (((uint32_t)(buf * BN + row) * XS + lk4) << 2);
            CP_ASYNC16(d, Bsrc + (size_t)row * K + lk4);
        }
    };

    float acc[4][4][4];
    #pragma unroll
    for (int mi = 0; mi < 4; mi++)
        #pragma unroll
        for (int ni = 0; ni < 4; ni++)
            #pragma unroll
            for (int q = 0; q < 4; q++) acc[mi][ni][q] = 0.0f;

    const int NSTAGE = K / BK;
    load_stage(0, 0);
    CP_COMMIT();

    for (int s = 0; s < NSTAGE; s++) {
        if (s + 1 < NSTAGE) {
            load_stage(s + 1, (s + 1) & 1);
            CP_COMMIT();
            CP_WAIT(1);
        } else {
            CP_WAIT(0);
        }
        __syncthreads();

        const float* Ab_s = Asf + (s & 1) * BM * XS;
        const float* Bb_s = Bsf + (s & 1) * BN * XS;
        #pragma unroll
        for (int kk = 0; kk < 4; kk++) {
            const int k8 = kk * 8;
            uint32_t afr[4][4], bfr[4][2];
            #pragma unroll
            for (int mi = 0; mi < 4; mi++) {
                // K-permuted layout: {k=tig, k=tig+4} are adjacent -> LDS.64
                const float* r0 = Ab_s + (wm0 + mi * 16 + gid) * XS + k8 + 2 * tig;
                float2 f0 = *(const float2*)r0;
                float2 f8 = *(const float2*)(r0 + 8 * XS);
                afr[mi][0] = __float_as_uint(f0.x);
                afr[mi][1] = __float_as_uint(f8.x);
                afr[mi][2] = __float_as_uint(f0.y);
                afr[mi][3] = __float_as_uint(f8.y);
            }
            #pragma unroll
            for (int ni = 0; ni < 4; ni++) {
                const float* rn = Bb_s + (wn0 + ni * 8 + gid) * XS + k8 + 2 * tig;
                float2 fn = *(const float2*)rn;
                bfr[ni][0] = __float_as_uint(fn.x);
                bfr[ni][1] = __float_as_uint(fn.y);
            }
            #pragma unroll
            for (int mi = 0; mi < 4; mi++)
                #pragma unroll
                for (int ni = 0; ni < 4; ni++)
                    mma_tf32(acc[mi][ni], afr[mi], bfr[ni]);
        }
        __syncthreads();
    }

    // Epilogue
    #pragma unroll
    for (int mi = 0; mi < 4; mi++) {
        #pragma unroll
        for (int ni = 0; ni < 4; ni++) {
            const int row = mbase + wm0 + mi * 16 + gid;
            const int col = nbase + wn0 + ni * 8 + tig * 2;
            float2 v0 = make_float2(acc[mi][ni][0], acc[mi][ni][1]);
            float2 v1 = make_float2(acc[mi][ni][2], acc[mi][ni][3]);
            *(float2*)(C + (size_t)row * N + col)       = v0;
            *(float2*)(C + (size_t)(row + 8) * N + col) = v1;
        }
    }
}

// ---------------------------------------------------------------------------
// Elementwise tf32 round + K-permute: out[perm(e)] = tf32(in[e])
// (permutation stays within 8-elem chunks; rows are 512-aligned so safe)
// ---------------------------------------------------------------------------
__global__ void round_perm_kernel(const float4* __restrict__ in,
                                  float* __restrict__ out, int n4)
{
    int i = blockIdx.x * blockDim.x + threadIdx.x;
    if (i < n4) {
        float4 v = in[i];
        int e = i * 4;
        int base = e & ~7;
        int lo = (e & 4) ? 1 : 0;   // second half of 8-chunk -> odd slots
        out[base + 0 + lo] = to_tf32(v.x);
        out[base + 2 + lo] = to_tf32(v.y);
        out[base + 4 + lo] = to_tf32(v.z);
        out[base + 6 + lo] = to_tf32(v.w);
    }
}

// ---------------------------------------------------------------------------
// Transpose + tf32 round + K-permute: out[c][perm(r)] = tf32(in[r][c])
// ---------------------------------------------------------------------------
__global__ void transpose_kernel(const float* __restrict__ in,
                                 float* __restrict__ out, int R, int C)
{
    __shared__ float tile[32][33];
    int x = blockIdx.x * 32 + threadIdx.x;
    int y = blockIdx.y * 32 + threadIdx.y;
    #pragma unroll
    for (int j = 0; j < 32; j += 8)
        tile[threadIdx.y + j][threadIdx.x] = in[(size_t)(y + j) * C + x];
    __syncthreads();
    x = blockIdx.y * 32 + threadIdx.x;   // indexes R (the K dim) -> permute
    y = blockIdx.x * 32 + threadIdx.y;
    const int xp = permk(x);
    #pragma unroll
    for (int j = 0; j < 32; j += 8)
        out[(size_t)(y + j) * R + xp] = to_tf32(tile[threadIdx.x][threadIdx.y + j]);
}

// ---------------------------------------------------------------------------
// Local attention: one warp per (row, head). Output tf32 + K-permuted
// (it is GEMM2's A operand).
// ---------------------------------------------------------------------------
__global__ __launch_bounds__(256) void local_attn_kernel(
    const float* __restrict__ qkv, const float* __restrict__ bias,
    float* __restrict__ out)
{
    const int gw   = blockIdx.x * 8 + (threadIdx.x >> 5);
    const int lane = threadIdx.x & 31;
    const int r = gw >> 3;
    const int h = gw & 7;
    const int s = r & (SEQ - 1);

    const float* qrow = qkv + (size_t)r * QKV_N + h * DK;
    const float q0 = qrow[lane];
    const float q1 = qrow[lane + 32];

    float logit[KSIZE];
    #pragma unroll
    for (int w = 0; w < KSIZE; w++) {
        const int sn = s + w - NEIGH;
        float dot = 0.0f;
        if (sn >= 0 && sn < SEQ) {
            const float* krow = qkv + (size_t)(r + w - NEIGH) * QKV_N
                                + HEADS * DK + h * DK;
            float t = q0 * krow[lane] + q1 * krow[lane + 32];
            #pragma unroll
            for (int off = 16; off > 0; off >>= 1)
                t += __shfl_xor_sync(0xFFFFFFFFu, t, off);
            dot = t;
        }
        logit[w] = dot * 0.125f + bias[((size_t)h * SEQ + s) * KSIZE + w];
    }

    float m = logit[0];
    #pragma unroll
    for (int w = 1; w < KSIZE; w++) m = fmaxf(m, logit[w]);
    float p[KSIZE];
    float denom = 0.0f;
    #pragma unroll
    for (int w = 0; w < KSIZE; w++) {
        p[w] = expf(logit[w] - m);
        denom += p[w];
    }
    const float inv = 1.0f / denom;

    float o0 = 0.0f, o1 = 0.0f;
    #pragma unroll
    for (int w = 0; w < KSIZE; w++) {
        const int sn = s + w - NEIGH;
        if (sn >= 0 && sn < SEQ) {
            const float* vrow = qkv + (size_t)(r + w - NEIGH) * QKV_N
                                + 2 * HEADS * DK + h * DK;
            o0 += p[w] * vrow[lane];
            o1 += p[w] * vrow[lane + 32];
        }
    }
    float* orow = out + (size_t)r * DMODEL;
    orow[permk(h * DK + lane)]      = to_tf32(o0 * inv);
    orow[permk(h * DK + lane + 32)] = to_tf32(o1 * inv);
}

// ---------------------------------------------------------------------------
// Launch
// ---------------------------------------------------------------------------
extern "C" void kernel_launch(void* const* d_in, const int* in_sizes, int n_in,
                              void* d_out, int out_size)
{
    const float* x    = (const float*)d_in[0];  // [2,64,256,512]
    const float* bias = (const float*)d_in[1];  // [8,256,7]
    const float* Wqkv = (const float*)d_in[2];  // [512,1536]
    const float* Wout = (const float*)d_in[3];  // [512,512]
    float* out        = (float*)d_out;          // [32768,512]

    float *xt, *qkv, *att, *wqkvT, *woutT;
    cudaGetSymbolAddress((void**)&xt,    g_xt);
    cudaGetSymbolAddress((void**)&qkv,   g_qkv);
    cudaGetSymbolAddress((void**)&att,   g_att);
    cudaGetSymbolAddress((void**)&wqkvT, g_wqkvT);
    cudaGetSymbolAddress((void**)&woutT, g_woutT);

    const int dyn_smem = 2 * (BM + BN) * XS * (int)sizeof(float);  // 73728
    static bool attr_done = false;
    if (!attr_done) {
        cudaFuncSetAttribute(gemm_mma_tf32,
                             cudaFuncAttributeMaxDynamicSharedMemorySize, dyn_smem);
        attr_done = true;
    }

    // 0) Pre-round+permute inputs / pre-transpose+round+permute weights
    {
        const int n4 = MROWS * DMODEL / 4;
        round_perm_kernel<<<(n4 + 255) / 256, 256>>>((const float4*)x, xt, n4);
        dim3 blk(32, 8);
        transpose_kernel<<<dim3(QKV_N / 32, DMODEL / 32), blk>>>(Wqkv, wqkvT,
                                                                 DMODEL, QKV_N);
        transpose_kernel<<<dim3(DMODEL / 32, DMODEL / 32), blk>>>(Wout, woutT,
                                                                  DMODEL, DMODEL);
    }

    // 1) QKV GEMM: [32768,512] @ [512,1536]
    {
        dim3 grid(QKV_N / BN, MROWS / BM);
        gemm_mma_tf32<<<grid, GEMM_THREADS, dyn_smem>>>(xt, wqkvT, qkv,
                                                        MROWS, QKV_N, DMODEL);
    }

    // 2) Local attention
    local_attn_kernel<<<MROWS, 256>>>(qkv, bias, att);

    // 3) Output GEMM: [32768,512] @ [512,512]
    {
        dim3 grid(DMODEL / BN, MROWS / BM);
        gemm_mma_tf32<<<grid, GEMM_THREADS, dyn_smem>>>(att, woutT, out,
                                                        MROWS, DMODEL, DMODEL);
    }
}

// round 5
// speedup vs baseline: 1.1818x; 1.1818x over previous
#include <cuda_runtime.h>
#include <cuda_bf16.h>
#include <math.h>
#include <stdint.h>

// Problem constants
#define BATCH   2
#define HW      64
#define SEQ     256
#define DMODEL  512
#define HEADS   8
#define DK      64
#define KSIZE   7
#define NEIGH   3

#define MROWS   (BATCH * HW * SEQ)      // 32768
#define QKV_N   (3 * HEADS * DK)        // 1536

// GEMM tiling
#define BM 128
#define BN 128
#define BK 32
#define XS 40   // smem row stride (floats); 40 mod 32 == 8 -> conflict-free LDS.64
#define GEMM_THREADS 256

// Scratch (allocation-free: __device__ globals)
__device__ float g_xt  [(size_t)MROWS * DMODEL];   //  64 MB (tf32, K-permuted)
__device__ float g_qkv [(size_t)MROWS * QKV_N];    // 201 MB
__device__ float g_att [(size_t)MROWS * DMODEL];   //  67 MB (tf32, K-permuted)
__device__ float g_wqkvT[(size_t)QKV_N * DMODEL];  //   3 MB (Wqkv^T, K-permuted)
__device__ float g_woutT[(size_t)DMODEL * DMODEL]; //   1 MB (Wout^T, K-permuted)

// ---------------------------------------------------------------------------
// Helpers
// ---------------------------------------------------------------------------
__device__ __forceinline__ float to_tf32(float x) {
    float y;
    asm("cvt.rna.tf32.f32 %0, %1;" : "=f"(y) : "f"(x));
    return y;
}

// In-8-chunk K permutation: k -> (k&~7) | ((k&3)<<1) | (k>>2&1).
// Applied to BOTH operands of each GEMM along K -> dot products invariant.
// Makes mma fragment k-pairs {t, t+4} adjacent in memory -> LDS.64.
__device__ __forceinline__ int permk(int k) {
    return (k & ~7) | ((k & 3) << 1) | ((k >> 2) & 1);
}

__device__ __forceinline__ uint32_t smem_u32(const void* p) {
    uint32_t a;
    asm("{ .reg .u64 t; cvta.to.shared.u64 t, %1; cvt.u32.u64 %0, t; }"
        : "=r"(a) : "l"(p));
    return a;
}

#define CP_ASYNC16(dst, src) \
    asm volatile("cp.async.cg.shared.global [%0], [%1], 16;" \
                 :: "r"(dst), "l"(src) : "memory")
#define CP_COMMIT() asm volatile("cp.async.commit_group;" ::: "memory")
#define CP_WAIT(n)  asm volatile("cp.async.wait_group %0;" :: "n"(n) : "memory")

__device__ __forceinline__ void mma_tf32(float* c, const uint32_t* a,
                                         const uint32_t* b) {
    asm volatile(
        "mma.sync.aligned.m16n8k8.row.col.f32.tf32.tf32.f32 "
        "{%0,%1,%2,%3}, {%4,%5,%6,%7}, {%8,%9}, {%0,%1,%2,%3};"
        : "+f"(c[0]), "+f"(c[1]), "+f"(c[2]), "+f"(c[3])
        : "r"(a[0]), "r"(a[1]), "r"(a[2]), "r"(a[3]),
          "r"(b[0]), "r"(b[1]));
}

// ---------------------------------------------------------------------------
// tf32 warp-MMA GEMM: C[M,N] = A[M,K] @ Bt[N,K]^T  (K-permuted operands)
// CTA 128x128, BK=32, double-buffered cp.async, 8 warps @ 64x32 warp tile.
// 2 CTAs/SM; XS=40 makes all fragment LDS.64 loads bank-conflict-free.
// ---------------------------------------------------------------------------
__global__ __launch_bounds__(GEMM_THREADS, 2) void gemm_mma_tf32(
    const float* __restrict__ A, const float* __restrict__ Bt,
    float* __restrict__ C, int M, int N, int K)
{
    extern __shared__ float sm[];
    float* Asf = sm;                       // [2][BM][XS]
    float* Bsf = sm + 2 * BM * XS;         // [2][BN][XS]
    const uint32_t as_u = smem_u32(Asf);
    const uint32_t bs_u = smem_u32(Bsf);

    const int tid  = threadIdx.x;
    const int wid  = tid >> 5;
    const int lane = tid & 31;
    const int gid  = lane >> 2;    // 0..7
    const int tig  = lane & 3;     // 0..3

    const int wm0 = (wid >> 2) * 64;   // warp m-offset in CTA tile
    const int wn0 = (wid & 3) * 32;    // warp n-offset

    const int mbase = blockIdx.y * BM;
    const int nbase = blockIdx.x * BN;
    const float* Ab = A  + (size_t)mbase * K;
    const float* Bb = Bt + (size_t)nbase * K;

    const int lrow = tid >> 3;          // 0..31
    const int lk4  = (tid & 7) << 2;    // 0,4,...,28

    auto load_stage = [&](int s, int buf) {
        const float* Asrc = Ab + (size_t)s * BK;
        const float* Bsrc = Bb + (size_t)s * BK;
        #pragma unroll
        for (int j = 0; j < 4; j++) {
            int row = lrow + 32 * j;
            uint32_t d = as_u + (((uint32_t)(buf * BM + row) * XS + lk4) << 2);
            CP_ASYNC16(d, Asrc + (size_t)row * K + lk4);
        }
        #pragma unroll
        for (int j = 0; j < 4; j++) {
            int row = lrow + 32 * j;
            uint32_t d = bs_u + (((uint32_t)(buf * BN + row) * XS + lk4) << 2);
            CP_ASYNC16(d, Bsrc + (size_t)row * K + lk4);
        }
    };

    float acc[4][4][4];
    #pragma unroll
    for (int mi = 0; mi < 4; mi++)
        #pragma unroll
        for (int ni = 0; ni < 4; ni++)
            #pragma unroll
            for (int q = 0; q < 4; q++) acc[mi][ni][q] = 0.0f;

    const int NSTAGE = K / BK;
    load_stage(0, 0);
    CP_COMMIT();

    for (int s = 0; s < NSTAGE; s++) {
        if (s + 1 < NSTAGE) {
            load_stage(s + 1, (s + 1) & 1);
            CP_COMMIT();
            CP_WAIT(1);
        } else {
            CP_WAIT(0);
        }
        __syncthreads();

        const float* Ab_s = Asf + (s & 1) * BM * XS;
        const float* Bb_s = Bsf + (s & 1) * BN * XS;
        #pragma unroll
        for (int kk = 0; kk < 4; kk++) {
            const int k8 = kk * 8;
            uint32_t afr[4][4], bfr[4][2];
            #pragma unroll
            for (int mi = 0; mi < 4; mi++) {
                // K-permuted: {k=tig, k=tig+4} adjacent -> single LDS.64
                const float* r0 = Ab_s + (wm0 + mi * 16 + gid) * XS + k8 + 2 * tig;
                float2 f0 = *(const float2*)r0;
                float2 f8 = *(const float2*)(r0 + 8 * XS);
                afr[mi][0] = __float_as_uint(f0.x);
                afr[mi][1] = __float_as_uint(f8.x);
                afr[mi][2] = __float_as_uint(f0.y);
                afr[mi][3] = __float_as_uint(f8.y);
            }
            #pragma unroll
            for (int ni = 0; ni < 4; ni++) {
                const float* rn = Bb_s + (wn0 + ni * 8 + gid) * XS + k8 + 2 * tig;
                float2 fn = *(const float2*)rn;
                bfr[ni][0] = __float_as_uint(fn.x);
                bfr[ni][1] = __float_as_uint(fn.y);
            }
            #pragma unroll
            for (int mi = 0; mi < 4; mi++)
                #pragma unroll
                for (int ni = 0; ni < 4; ni++)
                    mma_tf32(acc[mi][ni], afr[mi], bfr[ni]);
        }
        __syncthreads();
    }

    // Epilogue
    #pragma unroll
    for (int mi = 0; mi < 4; mi++) {
        #pragma unroll
        for (int ni = 0; ni < 4; ni++) {
            const int row = mbase + wm0 + mi * 16 + gid;
            const int col = nbase + wn0 + ni * 8 + tig * 2;
            float2 v0 = make_float2(acc[mi][ni][0], acc[mi][ni][1]);
            float2 v1 = make_float2(acc[mi][ni][2], acc[mi][ni][3]);
            *(float2*)(C + (size_t)row * N + col)       = v0;
            *(float2*)(C + (size_t)(row + 8) * N + col) = v1;
        }
    }
}

// ---------------------------------------------------------------------------
// Elementwise tf32 round + K-permute: out[perm(e)] = tf32(in[e])
// ---------------------------------------------------------------------------
__global__ void round_perm_kernel(const float4* __restrict__ in,
                                  float* __restrict__ out, int n4)
{
    int i = blockIdx.x * blockDim.x + threadIdx.x;
    if (i < n4) {
        float4 v = in[i];
        int e = i * 4;
        int base = e & ~7;
        int lo = (e & 4) ? 1 : 0;   // second half of 8-chunk -> odd slots
        out[base + 0 + lo] = to_tf32(v.x);
        out[base + 2 + lo] = to_tf32(v.y);
        out[base + 4 + lo] = to_tf32(v.z);
        out[base + 6 + lo] = to_tf32(v.w);
    }
}

// ---------------------------------------------------------------------------
// Transpose + tf32 round + K-permute: out[c][perm(r)] = tf32(in[r][c])
// ---------------------------------------------------------------------------
__global__ void transpose_kernel(const float* __restrict__ in,
                                 float* __restrict__ out, int R, int C)
{
    __shared__ float tile[32][33];
    int x = blockIdx.x * 32 + threadIdx.x;
    int y = blockIdx.y * 32 + threadIdx.y;
    #pragma unroll
    for (int j = 0; j < 32; j += 8)
        tile[threadIdx.y + j][threadIdx.x] = in[(size_t)(y + j) * C + x];
    __syncthreads();
    x = blockIdx.y * 32 + threadIdx.x;   // indexes R (the K dim) -> permute
    y = blockIdx.x * 32 + threadIdx.y;
    const int xp = permk(x);
    #pragma unroll
    for (int j = 0; j < 32; j += 8)
        out[(size_t)(y + j) * R + xp] = to_tf32(tile[threadIdx.x][threadIdx.y + j]);
}

// ---------------------------------------------------------------------------
// Local attention: one warp per (row, head). Output tf32 + K-permuted
// (it is GEMM2's A operand).
// ---------------------------------------------------------------------------
__global__ __launch_bounds__(256) void local_attn_kernel(
    const float* __restrict__ qkv, const float* __restrict__ bias,
    float* __restrict__ out)
{
    const int gw   = blockIdx.x * 8 + (threadIdx.x >> 5);
    const int lane = threadIdx.x & 31;
    const int r = gw >> 3;
    const int h = gw & 7;
    const int s = r & (SEQ - 1);

    const float* qrow = qkv + (size_t)r * QKV_N + h * DK;
    const float q0 = qrow[lane];
    const float q1 = qrow[lane + 32];

    float logit[KSIZE];
    #pragma unroll
    for (int w = 0; w < KSIZE; w++) {
        const int sn = s + w - NEIGH;
        float dot = 0.0f;
        if (sn >= 0 && sn < SEQ) {
            const float* krow = qkv + (size_t)(r + w - NEIGH) * QKV_N
                                + HEADS * DK + h * DK;
            float t = q0 * krow[lane] + q1 * krow[lane + 32];
            #pragma unroll
            for (int off = 16; off > 0; off >>= 1)
                t += __shfl_xor_sync(0xFFFFFFFFu, t, off);
            dot = t;
        }
        logit[w] = dot * 0.125f + bias[((size_t)h * SEQ + s) * KSIZE + w];
    }

    float m = logit[0];
    #pragma unroll
    for (int w = 1; w < KSIZE; w++) m = fmaxf(m, logit[w]);
    float p[KSIZE];
    float denom = 0.0f;
    #pragma unroll
    for (int w = 0; w < KSIZE; w++) {
        p[w] = expf(logit[w] - m);
        denom += p[w];
    }
    const float inv = 1.0f / denom;

    float o0 = 0.0f, o1 = 0.0f;
    #pragma unroll
    for (int w = 0; w < KSIZE; w++) {
        const int sn = s + w - NEIGH;
        if (sn >= 0 && sn < SEQ) {
            const float* vrow = qkv + (size_t)(r + w - NEIGH) * QKV_N
                                + 2 * HEADS * DK + h * DK;
            o0 += p[w] * vrow[lane];
            o1 += p[w] * vrow[lane + 32];
        }
    }
    float* orow = out + (size_t)r * DMODEL;
    orow[permk(h * DK + lane)]      = to_tf32(o0 * inv);
    orow[permk(h * DK + lane + 32)] = to_tf32(o1 * inv);
}

// ---------------------------------------------------------------------------
// Launch
// ---------------------------------------------------------------------------
extern "C" void kernel_launch(void* const* d_in, const int* in_sizes, int n_in,
                              void* d_out, int out_size)
{
    const float* x    = (const float*)d_in[0];  // [2,64,256,512]
    const float* bias = (const float*)d_in[1];  // [8,256,7]
    const float* Wqkv = (const float*)d_in[2];  // [512,1536]
    const float* Wout = (const float*)d_in[3];  // [512,512]
    float* out        = (float*)d_out;          // [32768,512]

    float *xt, *qkv, *att, *wqkvT, *woutT;
    cudaGetSymbolAddress((void**)&xt,    g_xt);
    cudaGetSymbolAddress((void**)&qkv,   g_qkv);
    cudaGetSymbolAddress((void**)&att,   g_att);
    cudaGetSymbolAddress((void**)&wqkvT, g_wqkvT);
    cudaGetSymbolAddress((void**)&woutT, g_woutT);

    const int dyn_smem = 2 * (BM + BN) * XS * (int)sizeof(float);  // 81920
    static bool attr_done = false;
    if (!attr_done) {
        cudaFuncSetAttribute(gemm_mma_tf32,
                             cudaFuncAttributeMaxDynamicSharedMemorySize, dyn_smem);
        attr_done = true;
    }

    // 0) Pre-round+permute inputs / pre-transpose+round+permute weights
    {
        const int n4 = MROWS * DMODEL / 4;
        round_perm_kernel<<<(n4 + 255) / 256, 256>>>((const float4*)x, xt, n4);
        dim3 blk(32, 8);
        transpose_kernel<<<dim3(QKV_N / 32, DMODEL / 32), blk>>>(Wqkv, wqkvT,
                                                                 DMODEL, QKV_N);
        transpose_kernel<<<dim3(DMODEL / 32, DMODEL / 32), blk>>>(Wout, woutT,
                                                                  DMODEL, DMODEL);
    }

    // 1) QKV GEMM: [32768,512] @ [512,1536]
    {
        dim3 grid(QKV_N / BN, MROWS / BM);
        gemm_mma_tf32<<<grid, GEMM_THREADS, dyn_smem>>>(xt, wqkvT, qkv,
                                                        MROWS, QKV_N, DMODEL);
    }

    // 2) Local attention
    local_attn_kernel<<<MROWS, 256>>>(qkv, bias, att);

    // 3) Output GEMM: [32768,512] @ [512,512]
    {
        dim3 grid(DMODEL / BN, MROWS / BM);
        gemm_mma_tf32<<<grid, GEMM_THREADS, dyn_smem>>>(att, woutT, out,
                                                        MROWS, DMODEL, DMODEL);
    }
}

// round 6
// speedup vs baseline: 1.2682x; 1.0731x over previous
#include <cuda_runtime.h>
#include <cuda_bf16.h>
#include <math.h>
#include <stdint.h>

// Problem constants
#define BATCH   2
#define HW      64
#define SEQ     256
#define DMODEL  512
#define HEADS   8
#define DK      64
#define KSIZE   7
#define NEIGH   3

#define MROWS   (BATCH * HW * SEQ)      // 32768
#define QKV_N   (3 * HEADS * DK)        // 1536

// GEMM tiling: CTA 128x128, 4 warps, warp tile 64x64
#define BM 128
#define BN 128
#define BK 32
#define XS 40   // smem row stride (floats); XS mod 32 == 8 -> conflict-free LDS.64
#define GEMM_THREADS 128

// Scratch (allocation-free: __device__ globals)
__device__ float g_xt  [(size_t)MROWS * DMODEL];   //  64 MB (tf32, K-permuted)
__device__ float g_qkv [(size_t)MROWS * QKV_N];    // 201 MB
__device__ float g_att [(size_t)MROWS * DMODEL];   //  67 MB (tf32, K-permuted)
__device__ float g_wqkvT[(size_t)QKV_N * DMODEL];  //   3 MB (Wqkv^T, K-permuted)
__device__ float g_woutT[(size_t)DMODEL * DMODEL]; //   1 MB (Wout^T, K-permuted)

// ---------------------------------------------------------------------------
// Helpers
// ---------------------------------------------------------------------------
__device__ __forceinline__ float to_tf32(float x) {
    float y;
    asm("cvt.rna.tf32.f32 %0, %1;" : "=f"(y) : "f"(x));
    return y;
}

// In-8-chunk K permutation: k -> (k&~7) | ((k&3)<<1) | (k>>2&1).
// Applied to BOTH operands of each GEMM along K -> dot products invariant.
// Makes mma fragment k-pairs {t, t+4} adjacent in memory -> LDS.64.
__device__ __forceinline__ int permk(int k) {
    return (k & ~7) | ((k & 3) << 1) | ((k >> 2) & 1);
}

__device__ __forceinline__ uint32_t smem_u32(const void* p) {
    uint32_t a;
    asm("{ .reg .u64 t; cvta.to.shared.u64 t, %1; cvt.u32.u64 %0, t; }"
        : "=r"(a) : "l"(p));
    return a;
}

#define CP_ASYNC16(dst, src) \
    asm volatile("cp.async.cg.shared.global [%0], [%1], 16;" \
                 :: "r"(dst), "l"(src) : "memory")
#define CP_COMMIT() asm volatile("cp.async.commit_group;" ::: "memory")
#define CP_WAIT(n)  asm volatile("cp.async.wait_group %0;" :: "n"(n) : "memory")

__device__ __forceinline__ void mma_tf32(float* c, const uint32_t* a,
                                         const uint32_t* b) {
    asm volatile(
        "mma.sync.aligned.m16n8k8.row.col.f32.tf32.tf32.f32 "
        "{%0,%1,%2,%3}, {%4,%5,%6,%7}, {%8,%9}, {%0,%1,%2,%3};"
        : "+f"(c[0]), "+f"(c[1]), "+f"(c[2]), "+f"(c[3])
        : "r"(a[0]), "r"(a[1]), "r"(a[2]), "r"(a[3]),
          "r"(b[0]), "r"(b[1]));
}

// ---------------------------------------------------------------------------
// tf32 warp-MMA GEMM: C[M,N] = A[M,K] @ Bt[N,K]^T  (K-permuted operands)
// CTA 128x128, 128 threads, 4 warps @ 64x64 warp tile (2x2 warp grid).
// Double-buffered cp.async, BK=32, 2 CTAs/SM, ~200 regs/thread (no cap).
// MMA:LDS.64 ratio = 2.0 (vs 1.33 at 64x32): smem crossbar floor halves.
// ---------------------------------------------------------------------------
__global__ __launch_bounds__(GEMM_THREADS, 2) void gemm_mma_tf32(
    const float* __restrict__ A, const float* __restrict__ Bt,
    float* __restrict__ C, int M, int N, int K)
{
    extern __shared__ float sm[];
    float* Asf = sm;                       // [2][BM][XS]
    float* Bsf = sm + 2 * BM * XS;         // [2][BN][XS]
    const uint32_t as_u = smem_u32(Asf);
    const uint32_t bs_u = smem_u32(Bsf);

    const int tid  = threadIdx.x;
    const int wid  = tid >> 5;
    const int lane = tid & 31;
    const int gid  = lane >> 2;    // 0..7
    const int tig  = lane & 3;     // 0..3

    const int wm0 = (wid >> 1) * 64;   // warp m-offset (0 or 64)
    const int wn0 = (wid & 1) * 64;    // warp n-offset (0 or 64)

    const int mbase = blockIdx.y * BM;
    const int nbase = blockIdx.x * BN;
    const float* Ab = A  + (size_t)mbase * K;
    const float* Bb = Bt + (size_t)nbase * K;

    const int lrow = tid >> 3;          // 0..15
    const int lk4  = (tid & 7) << 2;    // 0,4,...,28

    auto load_stage = [&](int s, int buf) {
        const float* Asrc = Ab + (size_t)s * BK;
        const float* Bsrc = Bb + (size_t)s * BK;
        #pragma unroll
        for (int j = 0; j < 8; j++) {
            int row = lrow + 16 * j;
            uint32_t d = as_u + (((uint32_t)(buf * BM + row) * XS + lk4) << 2);
            CP_ASYNC16(d, Asrc + (size_t)row * K + lk4);
        }
        #pragma unroll
        for (int j = 0; j < 8; j++) {
            int row = lrow + 16 * j;
            uint32_t d = bs_u + (((uint32_t)(buf * BN + row) * XS + lk4) << 2);
            CP_ASYNC16(d, Bsrc + (size_t)row * K + lk4);
        }
    };

    float acc[4][8][4];
    #pragma unroll
    for (int mi = 0; mi < 4; mi++)
        #pragma unroll
        for (int ni = 0; ni < 8; ni++)
            #pragma unroll
            for (int q = 0; q < 4; q++) acc[mi][ni][q] = 0.0f;

    const int NSTAGE = K / BK;
    load_stage(0, 0);
    CP_COMMIT();

    for (int s = 0; s < NSTAGE; s++) {
        if (s + 1 < NSTAGE) {
            load_stage(s + 1, (s + 1) & 1);
            CP_COMMIT();
            CP_WAIT(1);
        } else {
            CP_WAIT(0);
        }
        __syncthreads();

        const float* Ab_s = Asf + (s & 1) * BM * XS;
        const float* Bb_s = Bsf + (s & 1) * BN * XS;
        #pragma unroll
        for (int kk = 0; kk < 4; kk++) {
            const int k8 = kk * 8;
            uint32_t afr[4][4], bfr[8][2];
            #pragma unroll
            for (int mi = 0; mi < 4; mi++) {
                // K-permuted: {k=tig, k=tig+4} adjacent -> single LDS.64
                const float* r0 = Ab_s + (wm0 + mi * 16 + gid) * XS + k8 + 2 * tig;
                float2 f0 = *(const float2*)r0;
                float2 f8 = *(const float2*)(r0 + 8 * XS);
                afr[mi][0] = __float_as_uint(f0.x);
                afr[mi][1] = __float_as_uint(f8.x);
                afr[mi][2] = __float_as_uint(f0.y);
                afr[mi][3] = __float_as_uint(f8.y);
            }
            #pragma unroll
            for (int ni = 0; ni < 8; ni++) {
                const float* rn = Bb_s + (wn0 + ni * 8 + gid) * XS + k8 + 2 * tig;
                float2 fn = *(const float2*)rn;
                bfr[ni][0] = __float_as_uint(fn.x);
                bfr[ni][1] = __float_as_uint(fn.y);
            }
            #pragma unroll
            for (int mi = 0; mi < 4; mi++)
                #pragma unroll
                for (int ni = 0; ni < 8; ni++)
                    mma_tf32(acc[mi][ni], afr[mi], bfr[ni]);
        }
        __syncthreads();
    }

    // Epilogue
    #pragma unroll
    for (int mi = 0; mi < 4; mi++) {
        #pragma unroll
        for (int ni = 0; ni < 8; ni++) {
            const int row = mbase + wm0 + mi * 16 + gid;
            const int col = nbase + wn0 + ni * 8 + tig * 2;
            float2 v0 = make_float2(acc[mi][ni][0], acc[mi][ni][1]);
            float2 v1 = make_float2(acc[mi][ni][2], acc[mi][ni][3]);
            *(float2*)(C + (size_t)row * N + col)       = v0;
            *(float2*)(C + (size_t)(row + 8) * N + col) = v1;
        }
    }
}

// ---------------------------------------------------------------------------
// Elementwise tf32 round + K-permute: out[perm(e)] = tf32(in[e])
// ---------------------------------------------------------------------------
__global__ void round_perm_kernel(const float4* __restrict__ in,
                                  float* __restrict__ out, int n4)
{
    int i = blockIdx.x * blockDim.x + threadIdx.x;
    if (i < n4) {
        float4 v = in[i];
        int e = i * 4;
        int base = e & ~7;
        int lo = (e & 4) ? 1 : 0;   // second half of 8-chunk -> odd slots
        out[base + 0 + lo] = to_tf32(v.x);
        out[base + 2 + lo] = to_tf32(v.y);
        out[base + 4 + lo] = to_tf32(v.z);
        out[base + 6 + lo] = to_tf32(v.w);
    }
}

// ---------------------------------------------------------------------------
// Transpose + tf32 round + K-permute: out[c][perm(r)] = tf32(in[r][c])
// ---------------------------------------------------------------------------
__global__ void transpose_kernel(const float* __restrict__ in,
                                 float* __restrict__ out, int R, int C)
{
    __shared__ float tile[32][33];
    int x = blockIdx.x * 32 + threadIdx.x;
    int y = blockIdx.y * 32 + threadIdx.y;
    #pragma unroll
    for (int j = 0; j < 32; j += 8)
        tile[threadIdx.y + j][threadIdx.x] = in[(size_t)(y + j) * C + x];
    __syncthreads();
    x = blockIdx.y * 32 + threadIdx.x;   // indexes R (the K dim) -> permute
    y = blockIdx.x * 32 + threadIdx.y;
    const int xp = permk(x);
    #pragma unroll
    for (int j = 0; j < 32; j += 8)
        out[(size_t)(y + j) * R + xp] = to_tf32(tile[threadIdx.x][threadIdx.y + j]);
}

// ---------------------------------------------------------------------------
// Local attention: one warp per (row, head). Output tf32 + K-permuted
// (it is GEMM2's A operand).
// ---------------------------------------------------------------------------
__global__ __launch_bounds__(256) void local_attn_kernel(
    const float* __restrict__ qkv, const float* __restrict__ bias,
    float* __restrict__ out)
{
    const int gw   = blockIdx.x * 8 + (threadIdx.x >> 5);
    const int lane = threadIdx.x & 31;
    const int r = gw >> 3;
    const int h = gw & 7;
    const int s = r & (SEQ - 1);

    const float* qrow = qkv + (size_t)r * QKV_N + h * DK;
    const float q0 = qrow[lane];
    const float q1 = qrow[lane + 32];

    float logit[KSIZE];
    #pragma unroll
    for (int w = 0; w < KSIZE; w++) {
        const int sn = s + w - NEIGH;
        float dot = 0.0f;
        if (sn >= 0 && sn < SEQ) {
            const float* krow = qkv + (size_t)(r + w - NEIGH) * QKV_N
                                + HEADS * DK + h * DK;
            float t = q0 * krow[lane] + q1 * krow[lane + 32];
            #pragma unroll
            for (int off = 16; off > 0; off >>= 1)
                t += __shfl_xor_sync(0xFFFFFFFFu, t, off);
            dot = t;
        }
        logit[w] = dot * 0.125f + bias[((size_t)h * SEQ + s) * KSIZE + w];
    }

    float m = logit[0];
    #pragma unroll
    for (int w = 1; w < KSIZE; w++) m = fmaxf(m, logit[w]);
    float p[KSIZE];
    float denom = 0.0f;
    #pragma unroll
    for (int w = 0; w < KSIZE; w++) {
        p[w] = expf(logit[w] - m);
        denom += p[w];
    }
    const float inv = 1.0f / denom;

    float o0 = 0.0f, o1 = 0.0f;
    #pragma unroll
    for (int w = 0; w < KSIZE; w++) {
        const int sn = s + w - NEIGH;
        if (sn >= 0 && sn < SEQ) {
            const float* vrow = qkv + (size_t)(r + w - NEIGH) * QKV_N
                                + 2 * HEADS * DK + h * DK;
            o0 += p[w] * vrow[lane];
            o1 += p[w] * vrow[lane + 32];
        }
    }
    float* orow = out + (size_t)r * DMODEL;
    orow[permk(h * DK + lane)]      = to_tf32(o0 * inv);
    orow[permk(h * DK + lane + 32)] = to_tf32(o1 * inv);
}

// ---------------------------------------------------------------------------
// Launch
// ---------------------------------------------------------------------------
extern "C" void kernel_launch(void* const* d_in, const int* in_sizes, int n_in,
                              void* d_out, int out_size)
{
    const float* x    = (const float*)d_in[0];  // [2,64,256,512]
    const float* bias = (const float*)d_in[1];  // [8,256,7]
    const float* Wqkv = (const float*)d_in[2];  // [512,1536]
    const float* Wout = (const float*)d_in[3];  // [512,512]
    float* out        = (float*)d_out;          // [32768,512]

    float *xt, *qkv, *att, *wqkvT, *woutT;
    cudaGetSymbolAddress((void**)&xt,    g_xt);
    cudaGetSymbolAddress((void**)&qkv,   g_qkv);
    cudaGetSymbolAddress((void**)&att,   g_att);
    cudaGetSymbolAddress((void**)&wqkvT, g_wqkvT);
    cudaGetSymbolAddress((void**)&woutT, g_woutT);

    const int dyn_smem = 2 * (BM + BN) * XS * (int)sizeof(float);  // 81920
    static bool attr_done = false;
    if (!attr_done) {
        cudaFuncSetAttribute(gemm_mma_tf32,
                             cudaFuncAttributeMaxDynamicSharedMemorySize, dyn_smem);
        attr_done = true;
    }

    // 0) Pre-round+permute inputs / pre-transpose+round+permute weights
    {
        const int n4 = MROWS * DMODEL / 4;
        round_perm_kernel<<<(n4 + 255) / 256, 256>>>((const float4*)x, xt, n4);
        dim3 blk(32, 8);
        transpose_kernel<<<dim3(QKV_N / 32, DMODEL / 32), blk>>>(Wqkv, wqkvT,
                                                                 DMODEL, QKV_N);
        transpose_kernel<<<dim3(DMODEL / 32, DMODEL / 32), blk>>>(Wout, woutT,
                                                                  DMODEL, DMODEL);
    }

    // 1) QKV GEMM: [32768,512] @ [512,1536]
    {
        dim3 grid(QKV_N / BN, MROWS / BM);
        gemm_mma_tf32<<<grid, GEMM_THREADS, dyn_smem>>>(xt, wqkvT, qkv,
                                                        MROWS, QKV_N, DMODEL);
    }

    // 2) Local attention
    local_attn_kernel<<<MROWS, 256>>>(qkv, bias, att);

    // 3) Output GEMM: [32768,512] @ [512,512]
    {
        dim3 grid(DMODEL / BN, MROWS / BM);
        gemm_mma_tf32<<<grid, GEMM_THREADS, dyn_smem>>>(att, woutT, out,
                                                        MROWS, DMODEL, DMODEL);
    }
}

// round 7
// speedup vs baseline: 1.2941x; 1.0204x over previous
#include <cuda_runtime.h>
#include <cuda_bf16.h>
#include <math.h>
#include <stdint.h>

// Problem constants
#define BATCH   2
#define HW      64
#define SEQ     256
#define DMODEL  512
#define HEADS   8
#define DK      64
#define KSIZE   7
#define NEIGH   3

#define MROWS   (BATCH * HW * SEQ)      // 32768
#define QKV_N   (3 * HEADS * DK)        // 1536

// GEMM tiling: CTA 128x128, 4 warps, warp tile 64x64
#define BM 128
#define BN 128
#define BK 32
#define XS 40   // smem row stride (floats); XS mod 32 == 8 -> conflict-free LDS.64
#define GEMM_THREADS 128

// Scratch (allocation-free: __device__ globals)
__device__ float g_xt  [(size_t)MROWS * DMODEL];   //  64 MB (tf32, K-permuted)
__device__ float g_qkv [(size_t)MROWS * QKV_N];    // 201 MB
__device__ float g_att [(size_t)MROWS * DMODEL];   //  67 MB (tf32, K-permuted)
__device__ float g_wqkvT[(size_t)QKV_N * DMODEL];  //   3 MB (Wqkv^T, K-permuted)
__device__ float g_woutT[(size_t)DMODEL * DMODEL]; //   1 MB (Wout^T, K-permuted)

// ---------------------------------------------------------------------------
// Helpers
// ---------------------------------------------------------------------------
__device__ __forceinline__ float to_tf32(float x) {
    float y;
    asm("cvt.rna.tf32.f32 %0, %1;" : "=f"(y) : "f"(x));
    return y;
}

// In-8-chunk K permutation: k -> (k&~7) | ((k&3)<<1) | (k>>2&1).
// Applied to BOTH operands of each GEMM along K -> dot products invariant.
// Makes mma fragment k-pairs {t, t+4} adjacent in memory -> LDS.64.
__device__ __forceinline__ int permk(int k) {
    return (k & ~7) | ((k & 3) << 1) | ((k >> 2) & 1);
}

__device__ __forceinline__ uint32_t smem_u32(const void* p) {
    uint32_t a;
    asm("{ .reg .u64 t; cvta.to.shared.u64 t, %1; cvt.u32.u64 %0, t; }"
        : "=r"(a) : "l"(p));
    return a;
}

#define CP_ASYNC16(dst, src) \
    asm volatile("cp.async.cg.shared.global [%0], [%1], 16;" \
                 :: "r"(dst), "l"(src) : "memory")
#define CP_COMMIT() asm volatile("cp.async.commit_group;" ::: "memory")
#define CP_WAIT(n)  asm volatile("cp.async.wait_group %0;" :: "n"(n) : "memory")

__device__ __forceinline__ void mma_tf32(float* c, const uint32_t* a,
                                         const uint32_t* b) {
    asm volatile(
        "mma.sync.aligned.m16n8k8.row.col.f32.tf32.tf32.f32 "
        "{%0,%1,%2,%3}, {%4,%5,%6,%7}, {%8,%9}, {%0,%1,%2,%3};"
        : "+f"(c[0]), "+f"(c[1]), "+f"(c[2]), "+f"(c[3])
        : "r"(a[0]), "r"(a[1]), "r"(a[2]), "r"(a[3]),
          "r"(b[0]), "r"(b[1]));
}

// ---------------------------------------------------------------------------
// tf32 warp-MMA GEMM: C[M,N] = A[M,K] @ Bt[N,K]^T  (K-permuted operands)
// CTA 128x128, 128 threads, 4 warps @ 64x64 warp tile (2x2 warp grid).
// Double-buffered cp.async, BK=32, 2 CTAs/SM.
// ONE __syncthreads per K-stage: CP_WAIT -> bar -> issue loads(s+1) -> mma(s).
// The barrier both publishes stage-s data and protects buffer (s+1)&1
// (last read during compute(s-1), which precedes this barrier).
// ---------------------------------------------------------------------------
template<int K>
__global__ __launch_bounds__(GEMM_THREADS, 2) void gemm_mma_tf32(
    const float* __restrict__ A, const float* __restrict__ Bt,
    float* __restrict__ C, int M, int N)
{
    extern __shared__ float sm[];
    float* Asf = sm;                       // [2][BM][XS]
    float* Bsf = sm + 2 * BM * XS;         // [2][BN][XS]
    const uint32_t as_u = smem_u32(Asf);
    const uint32_t bs_u = smem_u32(Bsf);

    const int tid  = threadIdx.x;
    const int wid  = tid >> 5;
    const int lane = tid & 31;
    const int gid  = lane >> 2;    // 0..7
    const int tig  = lane & 3;     // 0..3

    const int wm0 = (wid >> 1) * 64;   // warp m-offset (0 or 64)
    const int wn0 = (wid & 1) * 64;    // warp n-offset (0 or 64)

    const int mbase = blockIdx.y * BM;
    const int nbase = blockIdx.x * BN;
    const float* Ab = A  + (size_t)mbase * K;
    const float* Bb = Bt + (size_t)nbase * K;

    const int lrow = tid >> 3;          // 0..15
    const int lk4  = (tid & 7) << 2;    // 0,4,...,28

    auto load_stage = [&](int s, int buf) {
        const float* Asrc = Ab + (size_t)s * BK;
        const float* Bsrc = Bb + (size_t)s * BK;
        #pragma unroll
        for (int j = 0; j < 8; j++) {
            int row = lrow + 16 * j;
            uint32_t d = as_u + (((uint32_t)(buf * BM + row) * XS + lk4) << 2);
            CP_ASYNC16(d, Asrc + (size_t)row * K + lk4);
        }
        #pragma unroll
        for (int j = 0; j < 8; j++) {
            int row = lrow + 16 * j;
            uint32_t d = bs_u + (((uint32_t)(buf * BN + row) * XS + lk4) << 2);
            CP_ASYNC16(d, Bsrc + (size_t)row * K + lk4);
        }
    };

    float acc[4][8][4];
    #pragma unroll
    for (int mi = 0; mi < 4; mi++)
        #pragma unroll
        for (int ni = 0; ni < 8; ni++)
            #pragma unroll
            for (int q = 0; q < 4; q++) acc[mi][ni][q] = 0.0f;

    const int NSTAGE = K / BK;
    load_stage(0, 0);
    CP_COMMIT();

    #pragma unroll 1
    for (int s = 0; s < NSTAGE; s++) {
        CP_WAIT(0);
        __syncthreads();

        if (s + 1 < NSTAGE) {
            load_stage(s + 1, (s + 1) & 1);
            CP_COMMIT();
        }

        const float* Ab_s = Asf + (s & 1) * BM * XS;
        const float* Bb_s = Bsf + (s & 1) * BN * XS;
        #pragma unroll
        for (int kk = 0; kk < 4; kk++) {
            const int k8 = kk * 8;
            uint32_t afr[4][4], bfr[8][2];
            #pragma unroll
            for (int mi = 0; mi < 4; mi++) {
                // K-permuted: {k=tig, k=tig+4} adjacent -> single LDS.64
                const float* r0 = Ab_s + (wm0 + mi * 16 + gid) * XS + k8 + 2 * tig;
                float2 f0 = *(const float2*)r0;
                float2 f8 = *(const float2*)(r0 + 8 * XS);
                afr[mi][0] = __float_as_uint(f0.x);
                afr[mi][1] = __float_as_uint(f8.x);
                afr[mi][2] = __float_as_uint(f0.y);
                afr[mi][3] = __float_as_uint(f8.y);
            }
            #pragma unroll
            for (int ni = 0; ni < 8; ni++) {
                const float* rn = Bb_s + (wn0 + ni * 8 + gid) * XS + k8 + 2 * tig;
                float2 fn = *(const float2*)rn;
                bfr[ni][0] = __float_as_uint(fn.x);
                bfr[ni][1] = __float_as_uint(fn.y);
            }
            #pragma unroll
            for (int mi = 0; mi < 4; mi++)
                #pragma unroll
                for (int ni = 0; ni < 8; ni++)
                    mma_tf32(acc[mi][ni], afr[mi], bfr[ni]);
        }
    }

    // Epilogue
    #pragma unroll
    for (int mi = 0; mi < 4; mi++) {
        #pragma unroll
        for (int ni = 0; ni < 8; ni++) {
            const int row = mbase + wm0 + mi * 16 + gid;
            const int col = nbase + wn0 + ni * 8 + tig * 2;
            float2 v0 = make_float2(acc[mi][ni][0], acc[mi][ni][1]);
            float2 v1 = make_float2(acc[mi][ni][2], acc[mi][ni][3]);
            *(float2*)(C + (size_t)row * N + col)       = v0;
            *(float2*)(C + (size_t)(row + 8) * N + col) = v1;
        }
    }
}

// ---------------------------------------------------------------------------
// Elementwise tf32 round + K-permute, one 8-chunk per thread, float4 I/O.
// Permuted chunk = {k0,k4,k1,k5,k2,k6,k3,k7}.
// ---------------------------------------------------------------------------
__global__ void round_perm_kernel(const float4* __restrict__ in,
                                  float4* __restrict__ out, int n8)
{
    int i = blockIdx.x * blockDim.x + threadIdx.x;
    if (i < n8) {
        float4 a = in[2 * i];
        float4 b = in[2 * i + 1];
        float4 o0 = make_float4(to_tf32(a.x), to_tf32(b.x),
                                to_tf32(a.y), to_tf32(b.y));
        float4 o1 = make_float4(to_tf32(a.z), to_tf32(b.z),
                                to_tf32(a.w), to_tf32(b.w));
        out[2 * i]     = o0;
        out[2 * i + 1] = o1;
    }
}

// ---------------------------------------------------------------------------
// Transpose + tf32 round + K-permute: out[c][perm(r)] = tf32(in[r][c])
// ---------------------------------------------------------------------------
__global__ void transpose_kernel(const float* __restrict__ in,
                                 float* __restrict__ out, int R, int C)
{
    __shared__ float tile[32][33];
    int x = blockIdx.x * 32 + threadIdx.x;
    int y = blockIdx.y * 32 + threadIdx.y;
    #pragma unroll
    for (int j = 0; j < 32; j += 8)
        tile[threadIdx.y + j][threadIdx.x] = in[(size_t)(y + j) * C + x];
    __syncthreads();
    x = blockIdx.y * 32 + threadIdx.x;   // indexes R (the K dim) -> permute
    y = blockIdx.x * 32 + threadIdx.y;
    const int xp = permk(x);
    #pragma unroll
    for (int j = 0; j < 32; j += 8)
        out[(size_t)(y + j) * R + xp] = to_tf32(tile[threadIdx.x][threadIdx.y + j]);
}

// ---------------------------------------------------------------------------
// Local attention: one warp per (row, head). Output tf32 + K-permuted
// (it is GEMM2's A operand).
// ---------------------------------------------------------------------------
__global__ __launch_bounds__(256) void local_attn_kernel(
    const float* __restrict__ qkv, const float* __restrict__ bias,
    float* __restrict__ out)
{
    const int gw   = blockIdx.x * 8 + (threadIdx.x >> 5);
    const int lane = threadIdx.x & 31;
    const int r = gw >> 3;
    const int h = gw & 7;
    const int s = r & (SEQ - 1);

    const float* qrow = qkv + (size_t)r * QKV_N + h * DK;
    const float q0 = qrow[lane];
    const float q1 = qrow[lane + 32];

    float logit[KSIZE];
    #pragma unroll
    for (int w = 0; w < KSIZE; w++) {
        const int sn = s + w - NEIGH;
        float dot = 0.0f;
        if (sn >= 0 && sn < SEQ) {
            const float* krow = qkv + (size_t)(r + w - NEIGH) * QKV_N
                                + HEADS * DK + h * DK;
            float t = q0 * krow[lane] + q1 * krow[lane + 32];
            #pragma unroll
            for (int off = 16; off > 0; off >>= 1)
                t += __shfl_xor_sync(0xFFFFFFFFu, t, off);
            dot = t;
        }
        logit[w] = dot * 0.125f + bias[((size_t)h * SEQ + s) * KSIZE + w];
    }

    float m = logit[0];
    #pragma unroll
    for (int w = 1; w < KSIZE; w++) m = fmaxf(m, logit[w]);
    float p[KSIZE];
    float denom = 0.0f;
    #pragma unroll
    for (int w = 0; w < KSIZE; w++) {
        p[w] = expf(logit[w] - m);
        denom += p[w];
    }
    const float inv = 1.0f / denom;

    float o0 = 0.0f, o1 = 0.0f;
    #pragma unroll
    for (int w = 0; w < KSIZE; w++) {
        const int sn = s + w - NEIGH;
        if (sn >= 0 && sn < SEQ) {
            const float* vrow = qkv + (size_t)(r + w - NEIGH) * QKV_N
                                + 2 * HEADS * DK + h * DK;
            o0 += p[w] * vrow[lane];
            o1 += p[w] * vrow[lane + 32];
        }
    }
    float* orow = out + (size_t)r * DMODEL;
    orow[permk(h * DK + lane)]      = to_tf32(o0 * inv);
    orow[permk(h * DK + lane + 32)] = to_tf32(o1 * inv);
}

// ---------------------------------------------------------------------------
// Launch
// ---------------------------------------------------------------------------
extern "C" void kernel_launch(void* const* d_in, const int* in_sizes, int n_in,
                              void* d_out, int out_size)
{
    const float* x    = (const float*)d_in[0];  // [2,64,256,512]
    const float* bias = (const float*)d_in[1];  // [8,256,7]
    const float* Wqkv = (const float*)d_in[2];  // [512,1536]
    const float* Wout = (const float*)d_in[3];  // [512,512]
    float* out        = (float*)d_out;          // [32768,512]

    float *xt, *qkv, *att, *wqkvT, *woutT;
    cudaGetSymbolAddress((void**)&xt,    g_xt);
    cudaGetSymbolAddress((void**)&qkv,   g_qkv);
    cudaGetSymbolAddress((void**)&att,   g_att);
    cudaGetSymbolAddress((void**)&wqkvT, g_wqkvT);
    cudaGetSymbolAddress((void**)&woutT, g_woutT);

    const int dyn_smem = 2 * (BM + BN) * XS * (int)sizeof(float);  // 81920
    static bool attr_done = false;
    if (!attr_done) {
        cudaFuncSetAttribute(gemm_mma_tf32<DMODEL>,
                             cudaFuncAttributeMaxDynamicSharedMemorySize, dyn_smem);
        attr_done = true;
    }

    // 0) Pre-round+permute inputs / pre-transpose+round+permute weights
    {
        const int n8 = MROWS * DMODEL / 8;
        round_perm_kernel<<<(n8 + 255) / 256, 256>>>((const float4*)x,
                                                     (float4*)xt, n8);
        dim3 blk(32, 8);
        transpose_kernel<<<dim3(QKV_N / 32, DMODEL / 32), blk>>>(Wqkv, wqkvT,
                                                                 DMODEL, QKV_N);
        transpose_kernel<<<dim3(DMODEL / 32, DMODEL / 32), blk>>>(Wout, woutT,
                                                                  DMODEL, DMODEL);
    }

    // 1) QKV GEMM: [32768,512] @ [512,1536]
    {
        dim3 grid(QKV_N / BN, MROWS / BM);
        gemm_mma_tf32<DMODEL><<<grid, GEMM_THREADS, dyn_smem>>>(xt, wqkvT, qkv,
                                                                MROWS, QKV_N);
    }

    // 2) Local attention
    local_attn_kernel<<<MROWS, 256>>>(qkv, bias, att);

    // 3) Output GEMM: [32768,512] @ [512,512]
    {
        dim3 grid(DMODEL / BN, MROWS / BM);
        gemm_mma_tf32<DMODEL><<<grid, GEMM_THREADS, dyn_smem>>>(att, woutT, out,
                                                                MROWS, DMODEL);
    }
}